// round 3
// baseline (speedup 1.0000x reference)
#include <cuda_runtime.h>

#define B_SZ 1024
#define T_SZ 512
#define F_SZ 124
#define NROWS (B_SZ * T_SZ)

// Scratch: pre-activations of layer0, laid out [t][b] as float4 (xyz = 3 hidden, w = pad)
// so the recurrence kernel reads fully coalesced per timestep. 8.4 MB -> L2-resident.
__device__ float4 g_pre[NROWS];

// ---------------------------------------------------------------------------
// Kernel A: pre[t][b][i] = dot(x[b,t,:], W_ih0[i,:]) + b_ih0[i] + b_hh0[i]
// Skinny GEMM, DRAM-bound (260 MB read). 256 threads/block, 256 rows/block,
// K processed in 32-wide chunks staged through padded shared memory.
// ---------------------------------------------------------------------------
__global__ __launch_bounds__(256) void pre_kernel(
    const float* __restrict__ x,
    const float* __restrict__ Wih0,
    const float* __restrict__ bih0,
    const float* __restrict__ bhh0)
{
    __shared__ float s[256 * 36];   // 256 rows x 32 cols, stride 36 (conflict-free LDS.128)
    __shared__ float sW[3 * 128];   // W_ih0 padded to 128 cols (pad = 0)

    const int tid = threadIdx.x;

    // Stage W (padded with zeros beyond col 123)
    for (int idx = tid; idx < 3 * 128; idx += 256) {
        int i = idx >> 7, cc = idx & 127;
        sW[idx] = (cc < F_SZ) ? Wih0[i * F_SZ + cc] : 0.0f;
    }
    const float bs0 = bih0[0] + bhh0[0];
    const float bs1 = bih0[1] + bhh0[1];
    const float bs2 = bih0[2] + bhh0[2];
    __syncthreads();

    const int row0 = blockIdx.x * 256;
    const int w    = tid >> 5;
    const int lane = tid & 31;
    const int lrbase = w * 32 + (lane >> 3);  // 4 rows per warp-instruction
    const int c4     = lane & 7;              // float4 column within chunk
    const float4* __restrict__ x4 = (const float4*)x;  // row stride = 31 float4 (496B, 16B-aligned)

    float acc0 = 0.f, acc1 = 0.f, acc2 = 0.f;

    #pragma unroll
    for (int kc = 0; kc < 124; kc += 32) {
        const int nc4 = (kc == 96) ? 7 : 8;   // last chunk: 28 cols

        // Stage: each warp loads its 32 rows' chunk, coalesced float4.
        if (c4 < nc4) {
            #pragma unroll
            for (int it = 0; it < 8; it++) {
                const int lr = lrbase + it * 4;
                float4 v = x4[(row0 + lr) * 31 + (kc >> 2) + c4];
                *(float4*)&s[lr * 36 + c4 * 4] = v;
            }
        }
        __syncthreads();

        // Compute: thread tid owns row tid; W loads are warp-broadcast LDS.128.
        #pragma unroll
        for (int cc = 0; cc < 8; cc++) {
            if (cc < nc4) {
                float4 v  = *(const float4*)&s[tid * 36 + cc * 4];
                float4 w0 = *(const float4*)&sW[0 * 128 + kc + cc * 4];
                float4 w1 = *(const float4*)&sW[1 * 128 + kc + cc * 4];
                float4 w2 = *(const float4*)&sW[2 * 128 + kc + cc * 4];
                acc0 += v.x * w0.x + v.y * w0.y + v.z * w0.z + v.w * w0.w;
                acc1 += v.x * w1.x + v.y * w1.y + v.z * w1.z + v.w * w1.w;
                acc2 += v.x * w2.x + v.y * w2.y + v.z * w2.z + v.w * w2.w;
            }
        }
        __syncthreads();
    }

    // Scatter to [t][b] layout (tiny write volume vs the 260MB read).
    const int row = row0 + tid;        // row = b*T + t (x is batch-major)
    const int b   = row >> 9;          // T = 512
    const int t   = row & 511;
    g_pre[t * B_SZ + b] = make_float4(acc0 + bs0, acc1 + bs1, acc2 + bs2, 0.0f);
}

// ---------------------------------------------------------------------------
// Kernel B: serial 2-layer tanh recurrence + final Linear. One thread per
// batch element; all weights in registers; tanh.approx.f32 on the critical
// path; 8-deep register prefetch ring hides L2 latency of pre[] loads.
// ---------------------------------------------------------------------------
__device__ __forceinline__ float tanha(float v) {
    float r;
    asm("tanh.approx.f32 %0, %1;" : "=f"(r) : "f"(v));
    return r;
}

__global__ __launch_bounds__(32) void rnn_kernel(
    const float* __restrict__ Whh0,
    const float* __restrict__ Wih1,
    const float* __restrict__ Whh1,
    const float* __restrict__ bih1,
    const float* __restrict__ bhh1,
    const float* __restrict__ Wfc,
    const float* __restrict__ bfc,
    float* __restrict__ out)
{
    const int b = blockIdx.x * 32 + threadIdx.x;   // 0..1023

    float a[9], c[9], d[9];
    #pragma unroll
    for (int i = 0; i < 9; i++) { a[i] = Whh0[i]; c[i] = Wih1[i]; d[i] = Whh1[i]; }
    float bb[3];
    #pragma unroll
    for (int i = 0; i < 3; i++) bb[i] = bih1[i] + bhh1[i];

    float h0x = 0.f, h0y = 0.f, h0z = 0.f;
    float h1x = 0.f, h1y = 0.f, h1z = 0.f;

    const int PF = 8;
    float4 buf[PF];
    #pragma unroll
    for (int i = 0; i < PF; i++) buf[i] = g_pre[i * B_SZ + b];

    #pragma unroll 8
    for (int t = 0; t < T_SZ; t++) {
        float4 p = buf[t & (PF - 1)];
        const int tn = t + PF;
        if (tn < T_SZ) buf[t & (PF - 1)] = g_pre[tn * B_SZ + b];

        const float n0x = tanha(p.x + a[0] * h0x + a[1] * h0y + a[2] * h0z);
        const float n0y = tanha(p.y + a[3] * h0x + a[4] * h0y + a[5] * h0z);
        const float n0z = tanha(p.z + a[6] * h0x + a[7] * h0y + a[8] * h0z);

        const float n1x = tanha(bb[0] + c[0] * n0x + c[1] * n0y + c[2] * n0z
                                      + d[0] * h1x + d[1] * h1y + d[2] * h1z);
        const float n1y = tanha(bb[1] + c[3] * n0x + c[4] * n0y + c[5] * n0z
                                      + d[3] * h1x + d[4] * h1y + d[5] * h1z);
        const float n1z = tanha(bb[2] + c[6] * n0x + c[7] * n0y + c[8] * n0z
                                      + d[6] * h1x + d[7] * h1y + d[8] * h1z);

        h0x = n0x; h0y = n0y; h0z = n0z;
        h1x = n1x; h1y = n1y; h1z = n1z;
    }

    // Final Linear on last h1: out[b][o] = b_fc[o] + dot(W_fc[o,:], h1)
    #pragma unroll
    for (int o = 0; o < 6; o++) {
        out[b * 6 + o] = bfc[o] + Wfc[o * 3 + 0] * h1x
                                + Wfc[o * 3 + 1] * h1y
                                + Wfc[o * 3 + 2] * h1z;
    }
}

extern "C" void kernel_launch(void* const* d_in, const int* in_sizes, int n_in,
                              void* d_out, int out_size)
{
    (void)in_sizes; (void)n_in; (void)out_size;
    const float* x    = (const float*)d_in[0];
    const float* Wih0 = (const float*)d_in[1];
    const float* Whh0 = (const float*)d_in[2];
    const float* bih0 = (const float*)d_in[3];
    const float* bhh0 = (const float*)d_in[4];
    const float* Wih1 = (const float*)d_in[5];
    const float* Whh1 = (const float*)d_in[6];
    const float* bih1 = (const float*)d_in[7];
    const float* bhh1 = (const float*)d_in[8];
    const float* Wfc  = (const float*)d_in[9];
    const float* bfc  = (const float*)d_in[10];
    float* out = (float*)d_out;

    pre_kernel<<<NROWS / 256, 256>>>(x, Wih0, bih0, bhh0);
    rnn_kernel<<<B_SZ / 32, 32>>>(Whh0, Wih1, Whh1, bih1, bhh1, Wfc, bfc, out);
}

// round 5
// speedup vs baseline: 1.2968x; 1.2968x over previous
#include <cuda_runtime.h>
#include <cstdint>

#define B_SZ 1024
#define T_SZ 512
#define F_SZ 124
#define NROWS (B_SZ * T_SZ)

// Pre-activations of layer0, [t][b] as float4 (xyz = hidden, w = pad). 8.4MB -> L2.
__device__ float4 g_pre[NROWS];

// ---------------------------------------------------------------------------
// Kernel A: pre[t][b][i] = dot(x[b,t,:], W_ih0[i,:]) + b_ih0[i] + b_hh0[i]
// DRAM-bound skinny GEMM. Per-warp smem staging, warp-local sync only.
// ---------------------------------------------------------------------------
__global__ __launch_bounds__(256) void pre_kernel(
    const float* __restrict__ x,
    const float* __restrict__ Wih0,
    const float* __restrict__ bih0,
    const float* __restrict__ bhh0)
{
    __shared__ float s[256 * 36];   // 256 rows x 32 cols, stride 36 (conflict-free LDS.128)
    __shared__ float sW[3 * 128];   // W_ih0 zero-padded to 128 cols

    const int tid = threadIdx.x;

    for (int idx = tid; idx < 3 * 128; idx += 256) {
        int i = idx >> 7, cc = idx & 127;
        sW[idx] = (cc < F_SZ) ? Wih0[i * F_SZ + cc] : 0.0f;
    }
    const float bs0 = bih0[0] + bhh0[0];
    const float bs1 = bih0[1] + bhh0[1];
    const float bs2 = bih0[2] + bhh0[2];
    __syncthreads();   // sW ready (only block-wide sync needed)

    const int row0 = blockIdx.x * 256;
    const int w    = tid >> 5;
    const int lane = tid & 31;
    const int lrbase = w * 32 + (lane >> 3);
    const int c4     = lane & 7;
    const float4* __restrict__ x4 = (const float4*)x;  // row stride 31 float4

    float acc0 = 0.f, acc1 = 0.f, acc2 = 0.f;

    #pragma unroll
    for (int kc = 0; kc < 124; kc += 32) {
        const int nc4 = (kc == 96) ? 7 : 8;

        if (c4 < nc4) {
            #pragma unroll
            for (int it = 0; it < 8; it++) {
                const int lr = lrbase + it * 4;
                float4 v = x4[(row0 + lr) * 31 + (kc >> 2) + c4];
                *(float4*)&s[lr * 36 + c4 * 4] = v;
            }
        }
        __syncwarp();   // warp w stages and reads only rows [w*32, w*32+32)

        #pragma unroll
        for (int cc = 0; cc < 8; cc++) {
            if (cc < nc4) {
                float4 v  = *(const float4*)&s[tid * 36 + cc * 4];
                float4 w0 = *(const float4*)&sW[0 * 128 + kc + cc * 4];
                float4 w1 = *(const float4*)&sW[1 * 128 + kc + cc * 4];
                float4 w2 = *(const float4*)&sW[2 * 128 + kc + cc * 4];
                acc0 += v.x * w0.x + v.y * w0.y + v.z * w0.z + v.w * w0.w;
                acc1 += v.x * w1.x + v.y * w1.y + v.z * w1.z + v.w * w1.w;
                acc2 += v.x * w2.x + v.y * w2.y + v.z * w2.z + v.w * w2.w;
            }
        }
        __syncwarp();
    }

    const int row = row0 + tid;     // row = b*T + t
    const int b   = row >> 9;
    const int t   = row & 511;
    g_pre[t * B_SZ + b] = make_float4(acc0 + bs0, acc1 + bs1, acc2 + bs2, 0.0f);
}

// ---------------------------------------------------------------------------
// Kernel B: warp-specialized recurrence.
//   8 blocks x 160 threads: warps 0-3 = 128 consumer threads (one batch elem
//   each), warp 4 = producer streaming g_pre into a 4-deep shared ring via
//   cp.async. Consumers have ZERO global loads -> no long-scoreboard aliasing
//   on the tanh/FMA chain.
// Ring: 4 stages x 8 timesteps x 128 float4 = 64KB dynamic smem.
// ---------------------------------------------------------------------------
#define CH    8                      // timesteps per chunk
#define NCHK  (T_SZ / CH)            // 64 chunks
#define NST   4                      // ring stages

__device__ __forceinline__ float tanha(float v) {
    float r;
    asm("tanh.approx.f32 %0, %1;" : "=f"(r) : "f"(v));
    return r;
}
__device__ __forceinline__ void cp_async16(unsigned int saddr, const void* gptr) {
    asm volatile("cp.async.cg.shared.global [%0], [%1], 16;" :: "r"(saddr), "l"(gptr));
}
#define CP_COMMIT() asm volatile("cp.async.commit_group;" ::: "memory")
#define CP_WAIT2()  asm volatile("cp.async.wait_group 2;"  ::: "memory")

__global__ __launch_bounds__(160) void rnn_kernel(
    const float* __restrict__ Whh0,
    const float* __restrict__ Wih1,
    const float* __restrict__ Whh1,
    const float* __restrict__ bih1,
    const float* __restrict__ bhh1,
    const float* __restrict__ Wfc,
    const float* __restrict__ bfc,
    float* __restrict__ out)
{
    extern __shared__ float4 ring[];   // [NST][CH][128]
    const int tid = threadIdx.x;
    const int wid = tid >> 5;
    const int b0  = blockIdx.x * 128;

    if (wid == 4) {
        // ---------------- producer warp ----------------
        const int lane = tid & 31;
        // pre-issue chunks 0..2 (one commit group per chunk)
        #pragma unroll
        for (int c = 0; c < NST - 1; c++) {
            #pragma unroll
            for (int r = 0; r < CH; r++) {
                const float4* src = &g_pre[(c * CH + r) * B_SZ + b0];
                float4* dst = &ring[(c * CH + r) * 128];
                #pragma unroll
                for (int j = 0; j < 4; j++) {
                    unsigned int sa = (unsigned int)__cvta_generic_to_shared(dst + j * 32 + lane);
                    cp_async16(sa, src + j * 32 + lane);
                }
            }
            CP_COMMIT();
        }
        for (int c = 0; c < NCHK; c++) {
            CP_WAIT2();            // chunks <= c complete
            __syncthreads();       // BAR_A: chunk c visible
            // overlap with consumer compute: issue chunk c+3 into stage (c+3)%4
            const int cn = c + NST - 1;
            if (cn < NCHK) {
                const int st = cn & (NST - 1);
                #pragma unroll
                for (int r = 0; r < CH; r++) {
                    const float4* src = &g_pre[(cn * CH + r) * B_SZ + b0];
                    float4* dst = &ring[(st * CH + r) * 128];
                    #pragma unroll
                    for (int j = 0; j < 4; j++) {
                        unsigned int sa = (unsigned int)__cvta_generic_to_shared(dst + j * 32 + lane);
                        cp_async16(sa, src + j * 32 + lane);
                    }
                }
            }
            CP_COMMIT();           // commit (possibly empty) to keep group count aligned
            __syncthreads();       // BAR_B: consumers done with chunk c
        }
    } else {
        // ---------------- consumer threads ----------------
        float a[9], c9[9], d9[9];
        #pragma unroll
        for (int i = 0; i < 9; i++) { a[i] = Whh0[i]; c9[i] = Wih1[i]; d9[i] = Whh1[i]; }
        float bb[3];
        #pragma unroll
        for (int i = 0; i < 3; i++) bb[i] = bih1[i] + bhh1[i];

        float h0x = 0.f, h0y = 0.f, h0z = 0.f;
        float h1x = 0.f, h1y = 0.f, h1z = 0.f;

        for (int c = 0; c < NCHK; c++) {
            __syncthreads();       // BAR_A
            const int st = c & (NST - 1);
            const float4* chunk = &ring[st * CH * 128];
            #pragma unroll
            for (int s = 0; s < CH; s++) {
                const float4 p = chunk[s * 128 + tid];   // LDS.128, conflict-free

                const float n0x = tanha(p.x + a[0] * h0x + a[1] * h0y + a[2] * h0z);
                const float n0y = tanha(p.y + a[3] * h0x + a[4] * h0y + a[5] * h0z);
                const float n0z = tanha(p.z + a[6] * h0x + a[7] * h0y + a[8] * h0z);

                // d-part first (depends only on previous h1 -> off the n0 path)
                float t0 = bb[0] + d9[0] * h1x + d9[1] * h1y + d9[2] * h1z;
                float t1 = bb[1] + d9[3] * h1x + d9[4] * h1y + d9[5] * h1z;
                float t2 = bb[2] + d9[6] * h1x + d9[7] * h1y + d9[8] * h1z;
                t0 += c9[0] * n0x + c9[1] * n0y + c9[2] * n0z;
                t1 += c9[3] * n0x + c9[4] * n0y + c9[5] * n0z;
                t2 += c9[6] * n0x + c9[7] * n0y + c9[8] * n0z;

                h1x = tanha(t0); h1y = tanha(t1); h1z = tanha(t2);
                h0x = n0x; h0y = n0y; h0z = n0z;
            }
            __syncthreads();       // BAR_B
        }

        const int b = b0 + tid;
        #pragma unroll
        for (int o = 0; o < 6; o++) {
            out[b * 6 + o] = bfc[o] + Wfc[o * 3 + 0] * h1x
                                    + Wfc[o * 3 + 1] * h1y
                                    + Wfc[o * 3 + 2] * h1z;
        }
    }
}

extern "C" void kernel_launch(void* const* d_in, const int* in_sizes, int n_in,
                              void* d_out, int out_size)
{
    (void)in_sizes; (void)n_in; (void)out_size;
    const float* x    = (const float*)d_in[0];
    const float* Wih0 = (const float*)d_in[1];
    const float* Whh0 = (const float*)d_in[2];
    const float* bih0 = (const float*)d_in[3];
    const float* bhh0 = (const float*)d_in[4];
    const float* Wih1 = (const float*)d_in[5];
    const float* Whh1 = (const float*)d_in[6];
    const float* bih1 = (const float*)d_in[7];
    const float* bhh1 = (const float*)d_in[8];
    const float* Wfc  = (const float*)d_in[9];
    const float* bfc  = (const float*)d_in[10];
    float* out = (float*)d_out;

    const int ring_bytes = NST * CH * 128 * sizeof(float4);   // 64KB
    static bool attr_set = false;
    if (!attr_set) {
        cudaFuncSetAttribute(rnn_kernel, cudaFuncAttributeMaxDynamicSharedMemorySize, ring_bytes);
        attr_set = true;
    }

    pre_kernel<<<NROWS / 256, 256>>>(x, Wih0, bih0, bhh0);
    rnn_kernel<<<B_SZ / 128, 160, ring_bytes>>>(Whh0, Wih1, Whh1, bih1, bhh1, Wfc, bfc, out);
}